// round 1
// baseline (speedup 1.0000x reference)
#include <cuda_runtime.h>

// Shapes (fixed by the problem):
//   x: [16,16,52,52] f32, W: [16,16,9,1] f32, B: [16,16,1] f32
//   out: [16,16,16] f32  (O, N, O) = out[b,c] + B[a,b]
#define NN 16
#define CC 16
#define HH 52
#define PLANE (HH*HH)      // 2704
#define KK 9
#define OH 50              // output window 50x50
#define M_TOT 22500.0f     // 9*2500

__device__ float g_S1[NN*CC*KK];
__device__ float g_S2[NN*CC*KK];
__device__ unsigned int g_count = 0;

__global__ void __launch_bounds__(256, 4)
tvar_fused_kernel(const float* __restrict__ x,
                  const float* __restrict__ W,
                  const float* __restrict__ B,
                  float* __restrict__ out)
{
    const int plane = blockIdx.x;                 // n*CC + c
    const float* xp = x + plane * PLANE;

    // ---- Phase 1: 9 window sums (S1) and square-sums (S2) per plane ----
    float a1[KK], a2[KK];
#pragma unroll
    for (int k = 0; k < KK; k++) { a1[k] = 0.f; a2[k] = 0.f; }

    for (int idx = threadIdx.x; idx < PLANE; idx += 256) {
        const int h = idx / HH;
        const int w = idx - h * HH;
        const float v  = __ldg(xp + idx);
        const float v2 = v * v;
#pragma unroll
        for (int i = 0; i < 3; i++) {
            const bool rok = (h >= i) && (h <= i + OH - 1);
#pragma unroll
            for (int j = 0; j < 3; j++) {
                const bool cok = (w >= j) && (w <= j + OH - 1);
                if (rok && cok) { a1[i*3+j] += v; a2[i*3+j] += v2; }
            }
        }
    }

    // warp reduction of 18 partials
#pragma unroll
    for (int k = 0; k < KK; k++) {
#pragma unroll
        for (int off = 16; off > 0; off >>= 1) {
            a1[k] += __shfl_down_sync(0xffffffffu, a1[k], off);
            a2[k] += __shfl_down_sync(0xffffffffu, a2[k], off);
        }
    }

    __shared__ float red[8][18];
    const int warp = threadIdx.x >> 5;
    const int lane = threadIdx.x & 31;
    if (lane == 0) {
#pragma unroll
        for (int k = 0; k < KK; k++) {
            red[warp][k]     = a1[k];
            red[warp][9 + k] = a2[k];
        }
    }
    __syncthreads();

    if (threadIdx.x < 18) {
        float s = 0.f;
#pragma unroll
        for (int wi = 0; wi < 8; wi++) s += red[wi][threadIdx.x];
        if (threadIdx.x < 9)  g_S1[plane * KK + threadIdx.x]       = s;
        else                  g_S2[plane * KK + (threadIdx.x - 9)] = s;
    }

    // ---- release: make S1/S2 device-visible, then count this block done ----
    __threadfence();
    __syncthreads();

    __shared__ int isLast;
    if (threadIdx.x == 0) {
        unsigned v = atomicAdd(&g_count, 1u);
        isLast = (v == gridDim.x - 1) ? 1 : 0;
    }
    __syncthreads();
    if (!isLast) return;

    // ---- Phase 2 (last block only): tiny contraction + broadcast epilogue ----
    if (threadIdx.x == 0) g_count = 0;   // reset for next graph replay
    __threadfence();                     // acquire side

    __shared__ float sW[NN*CC*KK];       // 2304 floats
    for (int i = threadIdx.x; i < NN*CC*KK; i += 256) sW[i] = __ldg(W + i);
    __syncthreads();

    const int n = threadIdx.x >> 4;      // 0..15
    const int o = threadIdx.x & 15;      // 0..15

    float acc = 0.f;
#pragma unroll 4
    for (int c = 0; c < CC; c++) {
        const float* wp = sW   + (o * CC + c) * KK;
        const float* s1 = g_S1 + (n * CC + c) * KK;
        const float* s2 = g_S2 + (n * CC + c) * KK;
        float size = 0.f, A = 0.f, Bs = 0.f;
#pragma unroll
        for (int k = 0; k < KK; k++) {
            const float w = wp[k];
            size += w;
            Bs = fmaf(w,     s1[k], Bs);
            A  = fmaf(w * w, s2[k], A);
        }
        acc += (A - Bs * Bs * (1.0f / M_TOT)) / size;
    }

    // out[a, n, o] = acc(n,o) + B[a, n]
#pragma unroll
    for (int a = 0; a < NN; a++)
        out[a * 256 + threadIdx.x] = acc + __ldg(B + a * CC + n);
}

extern "C" void kernel_launch(void* const* d_in, const int* in_sizes, int n_in,
                              void* d_out, int out_size)
{
    const float* x = (const float*)d_in[0];
    const float* W = (const float*)d_in[1];
    const float* B = (const float*)d_in[2];
    float* out = (float*)d_out;
    tvar_fused_kernel<<<NN * CC, 256>>>(x, W, B, out);
}

// round 2
// speedup vs baseline: 1.2293x; 1.2293x over previous
#include <cuda_runtime.h>

// Shapes (fixed): x:[16,16,52,52] f32, W:[16,16,9,1], B:[16,16,1], out:[16,16,16]
#define NN 16
#define CC 16
#define HH 52
#define PLANE (HH*HH)      // 2704 floats = 676 float4 (13 float4 per row)
#define VPP (PLANE/4)      // 676
#define KK 9
#define M_TOT 22500.0f

__device__ float g_contrib[NN*CC*16];   // [n][c][o]
__device__ unsigned int g_count = 0;

struct Acc { float t1, t2; };

__global__ void __launch_bounds__(256, 4)
tvar_kernel(const float* __restrict__ x, const float* __restrict__ W,
            const float* __restrict__ B, float* __restrict__ out)
{
    const int plane = blockIdx.x;          // n*16 + c
    const int n = plane >> 4;
    const int c = plane & 15;
    const int t = threadIdx.x;
    const float4* xv = (const float4*)(x + plane * PLANE);

    // ---- front-batched, vectorized loads (max MLP) ----
    float4 d0 = __ldg(xv + t);
    float4 d1 = __ldg(xv + t + 256);
    float4 d2 = make_float4(0.f, 0.f, 0.f, 0.f);
    const bool has2 = (t < VPP - 512);     // t < 164
    if (has2) d2 = __ldg(xv + t + 512);

    __shared__ float sRow1[4], sRow2[4], sCol1[4], sCol2[4];  // rows/cols {0,1,50,51}
    __shared__ float sCor1[16], sCor2[16];                    // 4x4 corner elements
    __shared__ float sS1[KK], sS2[KK];
    __shared__ float sWarp[8][2];
    if (t < 4) { sRow1[t] = 0.f; sRow2[t] = 0.f; sCol1[t] = 0.f; sCol2[t] = 0.f; }
    __syncthreads();

    float t1 = 0.f, t2 = 0.f;

    // process one row-aligned float4 at vec index q
    auto process = [&](int q, float4 v) {
        const float s1 = v.x + v.y + v.z + v.w;
        const float s2 = v.x*v.x + v.y*v.y + v.z*v.z + v.w*v.w;
        t1 += s1; t2 += s2;
        const int h  = q / 13;
        const int wq = q - h * 13;
        int ri = -1;
        if (h == 0) ri = 0; else if (h == 1) ri = 1;
        else if (h == 50) ri = 2; else if (h == 51) ri = 3;
        if (ri >= 0) { atomicAdd(&sRow1[ri], s1); atomicAdd(&sRow2[ri], s2); }
        if (wq == 0) {            // cols 0,1 in lanes x,y
            atomicAdd(&sCol1[0], v.x); atomicAdd(&sCol1[1], v.y);
            atomicAdd(&sCol2[0], v.x*v.x); atomicAdd(&sCol2[1], v.y*v.y);
            if (ri >= 0) {
                sCor1[ri*4+0] = v.x;     sCor1[ri*4+1] = v.y;
                sCor2[ri*4+0] = v.x*v.x; sCor2[ri*4+1] = v.y*v.y;
            }
        } else if (wq == 12) {    // cols 50,51 in lanes z,w
            atomicAdd(&sCol1[2], v.z); atomicAdd(&sCol1[3], v.w);
            atomicAdd(&sCol2[2], v.z*v.z); atomicAdd(&sCol2[3], v.w*v.w);
            if (ri >= 0) {
                sCor1[ri*4+2] = v.z;     sCor1[ri*4+3] = v.w;
                sCor2[ri*4+2] = v.z*v.z; sCor2[ri*4+3] = v.w*v.w;
            }
        }
    };

    process(t, d0);
    process(t + 256, d1);
    if (has2) process(t + 512, d2);

    // ---- block-wide totals ----
#pragma unroll
    for (int off = 16; off > 0; off >>= 1) {
        t1 += __shfl_down_sync(0xffffffffu, t1, off);
        t2 += __shfl_down_sync(0xffffffffu, t2, off);
    }
    const int warp = t >> 5, lane = t & 31;
    if (lane == 0) { sWarp[warp][0] = t1; sWarp[warp][1] = t2; }
    __syncthreads();

    // ---- 9 window sums via inclusion-exclusion (threads 0..8) ----
    if (t < 9) {
        float tot1 = 0.f, tot2 = 0.f;
#pragma unroll
        for (int wI = 0; wI < 8; wI++) { tot1 += sWarp[wI][0]; tot2 += sWarp[wI][1]; }
        const int i = t / 3, j = t % 3;
        // window rows [i, i+50): excluded strip rows (indices into {0,1,50,51})
        const float top1  = (i == 0) ? 0.f : (i == 1) ? sRow1[0] : sRow1[0] + sRow1[1];
        const float top2  = (i == 0) ? 0.f : (i == 1) ? sRow2[0] : sRow2[0] + sRow2[1];
        const float bot1  = (i == 0) ? sRow1[2] + sRow1[3] : (i == 1) ? sRow1[3] : 0.f;
        const float bot2  = (i == 0) ? sRow2[2] + sRow2[3] : (i == 1) ? sRow2[3] : 0.f;
        const float lef1  = (j == 0) ? 0.f : (j == 1) ? sCol1[0] : sCol1[0] + sCol1[1];
        const float lef2  = (j == 0) ? 0.f : (j == 1) ? sCol2[0] : sCol2[0] + sCol2[1];
        const float rig1  = (j == 0) ? sCol1[2] + sCol1[3] : (j == 1) ? sCol1[3] : 0.f;
        const float rig2  = (j == 0) ? sCol2[2] + sCol2[3] : (j == 1) ? sCol2[3] : 0.f;
        // corners: excluded-row x excluded-col pairs (add back once)
        const int er0 = (i == 0) ? 2 : 0;
        const int er1 = (i == 2) ? 1 : 3;
        const int ec0 = (j == 0) ? 2 : 0;
        const int ec1 = (j == 2) ? 1 : 3;
        const float co1 = sCor1[er0*4+ec0] + sCor1[er0*4+ec1]
                        + sCor1[er1*4+ec0] + sCor1[er1*4+ec1];
        const float co2 = sCor2[er0*4+ec0] + sCor2[er0*4+ec1]
                        + sCor2[er1*4+ec0] + sCor2[er1*4+ec1];
        sS1[t] = tot1 - top1 - bot1 - lef1 - rig1 + co1;
        sS2[t] = tot2 - top2 - bot2 - lef2 - rig2 + co2;
    }
    __syncthreads();

    // ---- per-block contribution for each output channel o ----
    if (t < 16) {
        const float* wp = W + (t * CC + c) * KK;   // W[o=t, c, :]
        float size = 0.f, A = 0.f, Bs = 0.f;
#pragma unroll
        for (int k = 0; k < KK; k++) {
            const float w = __ldg(wp + k);
            size += w;
            Bs = fmaf(w,     sS1[k], Bs);
            A  = fmaf(w * w, sS2[k], A);
        }
        g_contrib[(n * CC + c) * 16 + t] = (A - Bs * Bs * (1.0f / M_TOT)) / size;
    }
    __threadfence();
    __syncthreads();

    // ---- arrival; last block assembles the output ----
    __shared__ int isLast;
    if (t == 0) {
        unsigned v = atomicAdd(&g_count, 1u);
        isLast = (v == gridDim.x - 1) ? 1 : 0;
    }
    __syncthreads();
    if (!isLast) return;

    if (t == 0) g_count = 0;                // reset for next replay
    __threadfence();

    __shared__ float sB[256];
    sB[t] = __ldg(B + t);

    const int no = t >> 4;                  // n
    const int oo = t & 15;                  // o
    float acc = 0.f;
#pragma unroll
    for (int cc = 0; cc < 16; cc++)
        acc += __ldcg(&g_contrib[no * 256 + cc * 16 + oo]);   // L2-coherent reads

    __syncthreads();
#pragma unroll
    for (int a = 0; a < 16; a++)
        out[a * 256 + t] = acc + sB[a * 16 + no];
}

extern "C" void kernel_launch(void* const* d_in, const int* in_sizes, int n_in,
                              void* d_out, int out_size)
{
    const float* x = (const float*)d_in[0];
    const float* W = (const float*)d_in[1];
    const float* B = (const float*)d_in[2];
    float* out = (float*)d_out;
    tvar_kernel<<<NN * CC, 256>>>(x, W, B, out);
}